// round 13
// baseline (speedup 1.0000x reference)
#include <cuda_runtime.h>
#include <cuda_bf16.h>
#include <cstdint>
#include <math.h>

// ---------------------------------------------------------------------------
// Problem constants
// ---------------------------------------------------------------------------
#define B_  8
#define N_  2048
#define K_  64
#define TU_ 256
#define BNS 0.9995003746877732f   // np.float32(1/sqrt(1+1e-3))
#define QB  8
#define CAP 512
#define CHUNKS (CAP / 32)
#define M_  (B_ * N_)             // 16384 rows

// ---------------------------------------------------------------------------
// Static scratch
// ---------------------------------------------------------------------------
__device__ __align__(16) float g_xmax [B_ * TU_];
__device__ __align__(16) float g_T    [B_ * 9];
__device__ __align__(16) float g_pts  [B_ * N_ * 3];
__device__ __align__(16) float g_feats[(size_t)M_ * 576];
__device__ __align__(16) float g_bufA [(size_t)M_ * 512];
__device__ __align__(16) float g_bufB [(size_t)M_ * 512];
// bf16-split (hi|lo|hi along K) activation buffers + weight triples
__device__ __align__(16) __nv_bfloat16 g_a3a[(size_t)M_ * 1728];  // feats triple
__device__ __align__(16) __nv_bfloat16 g_a3b[(size_t)M_ * 1536];
__device__ __align__(16) __nv_bfloat16 g_a3c[(size_t)M_ * 1536];
__device__ __align__(16) __nv_bfloat16 g_w3 [2850816];
#define W3_C1 0
#define W3_R  884736
#define W3_B1 1671168
#define W3_B2 2457600

// ---------------------------------------------------------------------------
// T-net kernels (unchanged, verified)
// ---------------------------------------------------------------------------
__global__ void k_tnet_conv_max(const float* __restrict__ points,
                                const float* __restrict__ tw,
                                const float* __restrict__ tb,
                                const float* __restrict__ tg1,
                                const float* __restrict__ tbt1,
                                float* __restrict__ xmax)
{
    int b = blockIdx.x, ch = blockIdx.y;
    int u = threadIdx.x;
    float w0 = tw[u], w1 = tw[TU_ + u], w2 = tw[2 * TU_ + u];
    float bb = tb[u];
    float s  = __fmul_rn(tg1[u], BNS);
    float be = tbt1[u];
    float m = 0.f;
    int n0 = ch * 256;
    for (int n = n0; n < n0 + 256; n++) {
        const float* p = points + ((size_t)b * N_ + n) * 3;
        float v = __fadd_rn(__fadd_rn(__fmul_rn(p[0], w0), __fmul_rn(p[1], w1)),
                            __fmul_rn(p[2], w2));
        v = __fadd_rn(v, bb);
        v = __fadd_rn(__fmul_rn(v, s), be);
        v = fmaxf(v, 0.f);
        m = fmaxf(m, v);
    }
    atomicMax((int*)(xmax + b * TU_ + u), __float_as_int(m));
}

__global__ void k_tnet_dense(const float* __restrict__ xmax,
                             const float* __restrict__ td1w,
                             const float* __restrict__ td1b,
                             const float* __restrict__ tg2,
                             const float* __restrict__ tbt2,
                             const float* __restrict__ td2w,
                             const float* __restrict__ td2b,
                             float* __restrict__ Tm)
{
    __shared__ float xm[TU_];
    __shared__ float h[TU_];
    int b = blockIdx.x;
    int u = threadIdx.x;
    xm[u] = xmax[b * TU_ + u];
    __syncthreads();
    float acc = 0.f;
    for (int i = 0; i < TU_; i++)
        acc = __fadd_rn(acc, __fmul_rn(xm[i], td1w[i * TU_ + u]));
    acc = __fadd_rn(acc, td1b[u]);
    acc = __fadd_rn(__fmul_rn(acc, __fmul_rn(tg2[u], BNS)), tbt2[u]);
    h[u] = fmaxf(acc, 0.f);
    __syncthreads();
    if (u < 9) {
        float a2 = 0.f;
        for (int i = 0; i < TU_; i++)
            a2 = __fadd_rn(a2, __fmul_rn(h[i], td2w[i * 9 + u]));
        Tm[b * 9 + u] = __fadd_rn(a2, td2b[u]);
    }
}

__global__ void k_transform(const float* __restrict__ points,
                            const float* __restrict__ Tm,
                            float* __restrict__ pts)
{
    int idx = blockIdx.x * blockDim.x + threadIdx.x;
    if (idx >= B_ * N_) return;
    int b = idx >> 11;
    const float* T = Tm + b * 9;
    const float* p = points + (size_t)idx * 3;
    float p0 = p[0], p1 = p[1], p2 = p[2];
#pragma unroll
    for (int c = 0; c < 3; c++) {
        float v = __fadd_rn(__fadd_rn(__fmul_rn(p0, T[c]),
                                      __fmul_rn(p1, T[3 + c])),
                            __fmul_rn(p2, T[6 + c]));
        pts[(size_t)idx * 3 + c] = v;
    }
}

// ---------------------------------------------------------------------------
// Kernel 4: ball-query top-K (QB=8 queries/block, warp-per-query, CAP=512).
// Same algorithm as the verified R11 version; point staging dropped (gmem is
// L1/L2-hot: 24KB reused by 256 blocks) -> 40KB static smem, 5 blocks/SM.
// ---------------------------------------------------------------------------
__global__ __launch_bounds__(256)
void k_topk(const float* __restrict__ pts,
            const float* __restrict__ noise,
            float* __restrict__ feats)
{
    __shared__ unsigned long long ckey[QB * CAP];   // 32 KB
    __shared__ float dq128[QB * 128];               //  4 KB
    __shared__ float nq128[QB * 128];               //  4 KB
    __shared__ int cnt[QB];

    const float RADS[3] = {0.1f, 0.3f, 0.7f};

    int nbase = blockIdx.x * QB;
    int b = blockIdx.y;
    int tid = threadIdx.x;
    int lane = tid & 31, w = tid >> 5;

    const float* P = pts + (size_t)b * N_ * 3;

    if (tid < QB) cnt[tid] = 0;
    __syncthreads();

    float qx[QB], qy[QB], qz[QB];
#pragma unroll
    for (int q = 0; q < QB; q++) {
        qx[q] = P[3 * (nbase + q) + 0];
        qy[q] = P[3 * (nbase + q) + 1];
        qz[q] = P[3 * (nbase + q) + 2];
    }
    const float* nrowbase = noise + ((size_t)b * N_ + nbase) * N_;

    for (int i = tid; i < QB * 128; i += 256)
        nq128[i] = nrowbase[(size_t)(i >> 7) * N_ + (i & 127)];

    for (int e = tid; e < N_; e += 256) {
        float px = P[3 * e], py = P[3 * e + 1], pz = P[3 * e + 2];
#pragma unroll
        for (int q = 0; q < QB; q++) {
            float dx = qx[q] - px;
            float dy = qy[q] - py;
            float dz = qz[q] - pz;
            float s2 = __fadd_rn(__fadd_rn(__fmul_rn(dx, dx), __fmul_rn(dy, dy)),
                                 __fmul_rn(dz, dz));
            float d = __fsqrt_rn(s2);
            if (e < 128) dq128[q * 128 + e] = d;
            if (d <= 0.7f) {
                float nz = nrowbase[(size_t)q * N_ + e];
                if (nz > 0.0f) {
                    int slot = atomicAdd(&cnt[q], 1);
                    if (slot < CAP) {
                        ckey[q * CAP + slot] =
                            (((unsigned long long)__float_as_uint(nz)) << 32)
                            | (unsigned)(~e);
                    }
                }
            }
        }
    }
    __syncthreads();

    const int q = w;
    unsigned long long* kq = ckey + q * CAP;
    int C = min(cnt[q], CAP);
    int m = 1;
    while (m < C) m <<= 1;
    for (int i = C + lane; i < m; i += 32) kq[i] = 0ULL;
    __syncwarp();

    for (unsigned k2 = 2; k2 <= (unsigned)m; k2 <<= 1) {
        for (unsigned j = k2 >> 1; j > 0; j >>= 1) {
            for (int t = lane; t < m / 2; t += 32) {
                unsigned i = 2u * (unsigned)t - ((unsigned)t & (j - 1));
                unsigned p = i + j;
                bool up = (i & k2) != 0;
                unsigned long long a = kq[i], c = kq[p];
                if ((a < c) != up) { kq[i] = c; kq[p] = a; }
            }
            __syncwarp();
        }
    }

    float mqx = qx[q], mqy = qy[q], mqz = qz[q];
    int   jreg[CHUNKS];
    float dreg[CHUNKS];
#pragma unroll
    for (int c = 0; c < CHUNKS; c++) {
        int i = c * 32 + lane;
        if (i < C) {
            int jdx = (int)(~(unsigned)kq[i]);
            jreg[c] = jdx;
            float dx = mqx - P[3 * jdx + 0];
            float dy = mqy - P[3 * jdx + 1];
            float dz = mqz - P[3 * jdx + 2];
            float s2 = __fadd_rn(__fadd_rn(__fmul_rn(dx, dx), __fmul_rn(dy, dy)),
                                 __fmul_rn(dz, dz));
            dreg[c] = __fsqrt_rn(s2);
        } else {
            jreg[c] = 0;
            dreg[c] = 1e9f;
        }
    }

    size_t fbase = ((size_t)b * N_ + nbase + q) * 576;
    unsigned lmask = (1u << lane) - 1u;

    for (int r = 0; r < 3; r++) {
        float rad = RADS[r];
        int base = 0;
#pragma unroll
        for (int c = 0; c < CHUNKS; c++) {
            bool f = (dreg[c] <= rad);
            unsigned bal = __ballot_sync(0xffffffffu, f);
            int rank = base + __popc(bal & lmask);
            if (f && rank < K_) {
                int jdx = jreg[c];
                size_t fb = fbase + (size_t)rank * 9 + r * 3;
                feats[fb + 0] = P[3 * jdx + 0];
                feats[fb + 1] = P[3 * jdx + 1];
                feats[fb + 2] = P[3 * jdx + 2];
            }
            base += __popc(bal);
        }
        int top = (base < K_) ? base : K_;
        int R = K_ - top;
        if (R > 0) {
            int fb2 = 0;
            for (int c0 = 0; c0 < 128 && fb2 < R; c0 += 32) {
                int e = c0 + lane;
                bool isz = (dq128[q * 128 + e] > rad) ||
                           (nq128[q * 128 + e] <= 0.0f);
                unsigned bal = __ballot_sync(0xffffffffu, isz);
                int rank = fb2 + __popc(bal & lmask);
                if (isz && rank < R) {
                    size_t fb = fbase + (size_t)(top + rank) * 9 + r * 3;
                    feats[fb + 0] = P[3 * e + 0];
                    feats[fb + 1] = P[3 * e + 1];
                    feats[fb + 2] = P[3 * e + 2];
                }
                fb2 += __popc(bal);
            }
        }
    }
}

// ---------------------------------------------------------------------------
// bf16-split conversion kernels.
// Activations: A3[m] = [hi(0..K-1) | lo | hi]   (pairs with W3T = [hi|hi|lo])
// ---------------------------------------------------------------------------
__global__ void k_convA(const float* __restrict__ A,
                        __nv_bfloat16* __restrict__ A3, int K, int total)
{
    int idx = blockIdx.x * blockDim.x + threadIdx.x;
    if (idx >= total) return;
    int mrow = idx / K, k = idx - mrow * K;
    float a = A[idx];
    __nv_bfloat16 hi = __float2bfloat16_rn(a);
    __nv_bfloat16 lo = __float2bfloat16_rn(a - __bfloat162float(hi));
    size_t base = (size_t)mrow * 3 * K;
    A3[base + k] = hi;
    A3[base + K + k] = lo;
    A3[base + 2 * K + k] = hi;
}

// Weights: W [K][N] fp32 -> W3T [N][3K] bf16 = [hi | hi | lo] (k-contiguous)
__global__ void k_convW(const float* __restrict__ W,
                        __nv_bfloat16* __restrict__ W3T, int K, int N)
{
    int idx = blockIdx.x * blockDim.x + threadIdx.x;
    if (idx >= K * N) return;
    int k = idx / N, n = idx - k * N;
    float w = W[idx];
    __nv_bfloat16 hi = __float2bfloat16_rn(w);
    __nv_bfloat16 lo = __float2bfloat16_rn(w - __bfloat162float(hi));
    size_t base = (size_t)n * 3 * K;
    W3T[base + k] = hi;
    W3T[base + K + k] = hi;
    W3T[base + 2 * K + k] = lo;
}

// ---------------------------------------------------------------------------
// Tensor-core GEMM: C[M,N] = A3[M,Kt] x W3T[N,Kt]^T, fp32 accumulate via
// mma.sync.m16n8k16 bf16. BM=BN=128, BK=32, 8 warps (2x4), warp tile 64x32.
// EPI==1: BN+ReLU.  EPI==2: + bias + resid.
// Cf (fp32 out) and C3 (bf16 triple out, next layer's A3 with K=Kn) optional.
// ---------------------------------------------------------------------------
__device__ __forceinline__ void st_triple(__nv_bfloat16* C3, int row, int Kn,
                                          int col, float v0, float v1)
{
    __nv_bfloat16 h0 = __float2bfloat16_rn(v0);
    __nv_bfloat16 h1 = __float2bfloat16_rn(v1);
    __nv_bfloat16 l0 = __float2bfloat16_rn(v0 - __bfloat162float(h0));
    __nv_bfloat16 l1 = __float2bfloat16_rn(v1 - __bfloat162float(h1));
    size_t base = (size_t)row * 3 * Kn;
    __nv_bfloat162 hh; hh.x = h0; hh.y = h1;
    __nv_bfloat162 ll; ll.x = l0; ll.y = l1;
    *(__nv_bfloat162*)&C3[base + col] = hh;
    *(__nv_bfloat162*)&C3[base + Kn + col] = ll;
    *(__nv_bfloat162*)&C3[base + 2 * Kn + col] = hh;
}

#define MMA16816(c, a, b)                                                   \
    asm volatile("mma.sync.aligned.m16n8k16.row.col.f32.bf16.bf16.f32 "     \
                 "{%0,%1,%2,%3},{%4,%5,%6,%7},{%8,%9},{%0,%1,%2,%3};"       \
                 : "+f"((c)[0]), "+f"((c)[1]), "+f"((c)[2]), "+f"((c)[3])   \
                 : "r"((a)[0]), "r"((a)[1]), "r"((a)[2]), "r"((a)[3]),      \
                   "r"((b)[0]), "r"((b)[1]))

template <int EPI>
__global__ __launch_bounds__(256, 2)
void k_mma(const __nv_bfloat16* __restrict__ A3,
           const __nv_bfloat16* __restrict__ W3T,
           const float* __restrict__ bias, const float* __restrict__ gamma,
           const float* __restrict__ beta, const float* __restrict__ resid,
           float* __restrict__ Cf, __nv_bfloat16* __restrict__ C3,
           int N, int Kt, int Kn)
{
    __shared__ __nv_bfloat16 As[2][128][34];
    __shared__ __nv_bfloat16 Bs[2][128][34];

    const int tid = threadIdx.x;
    const int m0 = blockIdx.y * 128;
    const int n0 = blockIdx.x * 128;
    const int warp = tid >> 5, lane = tid & 31;
    const int g = lane >> 2, t = lane & 3;
    const int wm = warp >> 2, wn = warp & 3;     // 2 x 4 warp grid

    const int lrow = tid >> 1;
    const int lko  = (tid & 1) * 16;

    float acc[4][4][4] = {};

    const __nv_bfloat16* Ag = A3 + (size_t)(m0 + lrow) * Kt + lko;
    const __nv_bfloat16* Bg = W3T + (size_t)(n0 + lrow) * Kt + lko;

    uint4 ra0, ra1, rb0, rb1;
    ra0 = *(const uint4*)(Ag);
    ra1 = *(const uint4*)(Ag + 8);
    rb0 = *(const uint4*)(Bg);
    rb1 = *(const uint4*)(Bg + 8);
    int cur = 0;
    {
        unsigned* as = (unsigned*)&As[0][lrow][lko];
        as[0] = ra0.x; as[1] = ra0.y; as[2] = ra0.z; as[3] = ra0.w;
        as[4] = ra1.x; as[5] = ra1.y; as[6] = ra1.z; as[7] = ra1.w;
        unsigned* bs = (unsigned*)&Bs[0][lrow][lko];
        bs[0] = rb0.x; bs[1] = rb0.y; bs[2] = rb0.z; bs[3] = rb0.w;
        bs[4] = rb1.x; bs[5] = rb1.y; bs[6] = rb1.z; bs[7] = rb1.w;
    }
    __syncthreads();

    const int nIter = Kt >> 5;
    for (int it = 0; it < nIter; ++it) {
        bool nxt = (it + 1 < nIter);
        if (nxt) {
            const __nv_bfloat16* ag = Ag + (size_t)(it + 1) * 32;
            const __nv_bfloat16* bg = Bg + (size_t)(it + 1) * 32;
            ra0 = *(const uint4*)(ag);
            ra1 = *(const uint4*)(ag + 8);
            rb0 = *(const uint4*)(bg);
            rb1 = *(const uint4*)(bg + 8);
        }
#pragma unroll
        for (int kh = 0; kh < 2; ++kh) {
            unsigned af[4][4], bf[4][2];
            int kb = kh * 16 + 2 * t;
#pragma unroll
            for (int i = 0; i < 4; ++i) {
                int r0 = wm * 64 + i * 16 + g;
                af[i][0] = *(const unsigned*)&As[cur][r0][kb];
                af[i][1] = *(const unsigned*)&As[cur][r0 + 8][kb];
                af[i][2] = *(const unsigned*)&As[cur][r0][kb + 8];
                af[i][3] = *(const unsigned*)&As[cur][r0 + 8][kb + 8];
            }
#pragma unroll
            for (int j = 0; j < 4; ++j) {
                int nn = wn * 32 + j * 8 + g;
                bf[j][0] = *(const unsigned*)&Bs[cur][nn][kb];
                bf[j][1] = *(const unsigned*)&Bs[cur][nn][kb + 8];
            }
#pragma unroll
            for (int i = 0; i < 4; ++i)
#pragma unroll
                for (int j = 0; j < 4; ++j)
                    MMA16816(acc[i][j], af[i], bf[j]);
        }
        if (nxt) {
            int nb = cur ^ 1;
            unsigned* as = (unsigned*)&As[nb][lrow][lko];
            as[0] = ra0.x; as[1] = ra0.y; as[2] = ra0.z; as[3] = ra0.w;
            as[4] = ra1.x; as[5] = ra1.y; as[6] = ra1.z; as[7] = ra1.w;
            unsigned* bs = (unsigned*)&Bs[nb][lrow][lko];
            bs[0] = rb0.x; bs[1] = rb0.y; bs[2] = rb0.z; bs[3] = rb0.w;
            bs[4] = rb1.x; bs[5] = rb1.y; bs[6] = rb1.z; bs[7] = rb1.w;
            __syncthreads();
            cur = nb;
        }
    }

    // epilogue
#pragma unroll
    for (int i = 0; i < 4; ++i) {
        int r0 = m0 + wm * 64 + i * 16 + g;
#pragma unroll
        for (int j = 0; j < 4; ++j) {
            int col = n0 + wn * 32 + j * 8 + 2 * t;
            float* c = acc[i][j];
            float v00, v01, v10, v11;
            float2 bv = *(const float2*)&bias[col];
            if (EPI == 1) {
                float2 gv = *(const float2*)&gamma[col];
                float2 ev = *(const float2*)&beta[col];
                float gs0 = gv.x * BNS, gs1 = gv.y * BNS;
                v00 = fmaxf((c[0] + bv.x) * gs0 + ev.x, 0.f);
                v01 = fmaxf((c[1] + bv.y) * gs1 + ev.y, 0.f);
                v10 = fmaxf((c[2] + bv.x) * gs0 + ev.x, 0.f);
                v11 = fmaxf((c[3] + bv.y) * gs1 + ev.y, 0.f);
            } else {
                float2 r0v = *(const float2*)&resid[(size_t)r0 * N + col];
                float2 r1v = *(const float2*)&resid[(size_t)(r0 + 8) * N + col];
                v00 = c[0] + bv.x + r0v.x;
                v01 = c[1] + bv.y + r0v.y;
                v10 = c[2] + bv.x + r1v.x;
                v11 = c[3] + bv.y + r1v.y;
            }
            if (Cf) {
                *(float2*)&Cf[(size_t)r0 * N + col] = make_float2(v00, v01);
                *(float2*)&Cf[(size_t)(r0 + 8) * N + col] = make_float2(v10, v11);
            }
            if (C3) {
                st_triple(C3, r0, Kn, col, v00, v01);
                st_triple(C3, r0 + 8, Kn, col, v10, v11);
            }
        }
    }
}

// ---------------------------------------------------------------------------
// SIMT GEMM (kept for b3 + fused maxpool; EPI==3 path verified)
// ---------------------------------------------------------------------------
template <int EPI>
__global__ __launch_bounds__(256, 2)
void k_gemm128(const float* __restrict__ A, const float* __restrict__ W,
               const float* __restrict__ bias, const float* __restrict__ gamma,
               const float* __restrict__ beta, const float* __restrict__ resid,
               float* __restrict__ C, int M, int N, int Kd)
{
    __shared__ __align__(16) float As[2][8][132];
    __shared__ __align__(16) float Ws[2][8][128];

    const int tid = threadIdx.x;
    const int tx = tid & 15;
    const int ty = tid >> 4;
    const int m0 = blockIdx.y * 128;
    const int n0 = blockIdx.x * 128;

    const int arow = tid >> 1;
    const int akh  = (tid & 1) * 4;
    const int bkk = tid >> 5;
    const int bn  = (tid & 31) * 4;
    const bool nvec = ((N & 3) == 0);

    float4 areg, breg;
    float acc[8][8];
#pragma unroll
    for (int i = 0; i < 8; i++)
#pragma unroll
        for (int j = 0; j < 8; j++) acc[i][j] = 0.f;

    areg = *(const float4*)&A[(size_t)(m0 + arow) * Kd + akh];
    {
        const float* wp = &W[(size_t)bkk * N];
        int col = n0 + bn;
        if (nvec && col + 3 < N) breg = *(const float4*)&wp[col];
        else {
            breg.x = (col + 0 < N) ? wp[col + 0] : 0.f;
            breg.y = (col + 1 < N) ? wp[col + 1] : 0.f;
            breg.z = (col + 2 < N) ? wp[col + 2] : 0.f;
            breg.w = (col + 3 < N) ? wp[col + 3] : 0.f;
        }
    }
    int cur = 0;
    As[0][akh + 0][arow] = areg.x;
    As[0][akh + 1][arow] = areg.y;
    As[0][akh + 2][arow] = areg.z;
    As[0][akh + 3][arow] = areg.w;
    *(float4*)&Ws[0][bkk][bn] = breg;
    __syncthreads();

    for (int k0 = 0; k0 < Kd; k0 += 8) {
        bool has_next = (k0 + 8 < Kd);
        if (has_next) {
            areg = *(const float4*)&A[(size_t)(m0 + arow) * Kd + k0 + 8 + akh];
            const float* wp = &W[(size_t)(k0 + 8 + bkk) * N];
            int col = n0 + bn;
            if (nvec && col + 3 < N) breg = *(const float4*)&wp[col];
            else {
                breg.x = (col + 0 < N) ? wp[col + 0] : 0.f;
                breg.y = (col + 1 < N) ? wp[col + 1] : 0.f;
                breg.z = (col + 2 < N) ? wp[col + 2] : 0.f;
                breg.w = (col + 3 < N) ? wp[col + 3] : 0.f;
            }
        }
#pragma unroll
        for (int kk = 0; kk < 8; kk++) {
            float4 a0 = *(const float4*)&As[cur][kk][ty * 4];
            float4 a1 = *(const float4*)&As[cur][kk][64 + ty * 4];
            float4 b0 = *(const float4*)&Ws[cur][kk][tx * 4];
            float4 b1 = *(const float4*)&Ws[cur][kk][64 + tx * 4];
            float av[8] = {a0.x, a0.y, a0.z, a0.w, a1.x, a1.y, a1.z, a1.w};
            float bv[8] = {b0.x, b0.y, b0.z, b0.w, b1.x, b1.y, b1.z, b1.w};
#pragma unroll
            for (int i = 0; i < 8; i++)
#pragma unroll
                for (int j = 0; j < 8; j++)
                    acc[i][j] += av[i] * bv[j];
        }
        if (has_next) {
            int nxt = cur ^ 1;
            As[nxt][akh + 0][arow] = areg.x;
            As[nxt][akh + 1][arow] = areg.y;
            As[nxt][akh + 2][arow] = areg.z;
            As[nxt][akh + 3][arow] = areg.w;
            *(float4*)&Ws[nxt][bkk][bn] = breg;
            __syncthreads();
            cur = nxt;
        }
    }

    if (EPI == 3) {
        int bidx = m0 >> 11;
#pragma unroll
        for (int jh = 0; jh < 2; jh++)
#pragma unroll
            for (int j = 0; j < 4; j++) {
                int col = n0 + jh * 64 + tx * 4 + j;
                if (col < N) {
                    float gs = gamma[col] * BNS;
                    float bt = beta[col];
                    float bs = bias[col];
                    float mv = 0.f;
#pragma unroll
                    for (int ii = 0; ii < 8; ii++) {
                        float v = fmaxf((acc[ii][jh * 4 + j] + bs) * gs + bt, 0.f);
                        mv = fmaxf(mv, v);
                    }
                    atomicMax((int*)&C[(size_t)bidx * 170 + col],
                              __float_as_int(mv));
                }
            }
    } else {
#pragma unroll
        for (int ih = 0; ih < 2; ih++)
#pragma unroll
            for (int i = 0; i < 4; i++) {
                int row = m0 + ih * 64 + ty * 4 + i;
#pragma unroll
                for (int jh = 0; jh < 2; jh++)
#pragma unroll
                    for (int j = 0; j < 4; j++) {
                        int col = n0 + jh * 64 + tx * 4 + j;
                        if (col < N) {
                            float v = acc[ih * 4 + i][jh * 4 + j] + bias[col];
                            if (EPI == 1) {
                                v = v * (gamma[col] * BNS) + beta[col];
                                v = fmaxf(v, 0.f);
                            } else {
                                v += resid[(size_t)row * N + col];
                            }
                            C[(size_t)row * N + col] = v;
                        }
                    }
            }
    }
}

// ---------------------------------------------------------------------------
// Launch
// ---------------------------------------------------------------------------
extern "C" void kernel_launch(void* const* d_in, const int* in_sizes, int n_in,
                              void* d_out, int out_size)
{
    const float* points = (const float*)d_in[0];
    const float* noise  = (const float*)d_in[1];
    const float* tw     = (const float*)d_in[2];
    const float* tb     = (const float*)d_in[3];
    const float* tg1    = (const float*)d_in[4];
    const float* tbt1   = (const float*)d_in[5];
    const float* td1w   = (const float*)d_in[6];
    const float* td1b   = (const float*)d_in[7];
    const float* tg2    = (const float*)d_in[8];
    const float* tbt2   = (const float*)d_in[9];
    const float* td2w   = (const float*)d_in[10];
    const float* td2b   = (const float*)d_in[11];
    const float* c1w    = (const float*)d_in[12];
    const float* c1b    = (const float*)d_in[13];
    const float* g1     = (const float*)d_in[14];
    const float* be1    = (const float*)d_in[15];
    const float* rw     = (const float*)d_in[16];
    const float* rb     = (const float*)d_in[17];
    const float* b1w    = (const float*)d_in[18];
    const float* b1b    = (const float*)d_in[19];
    const float* b1g    = (const float*)d_in[20];
    const float* b1be   = (const float*)d_in[21];
    const float* b2w    = (const float*)d_in[22];
    const float* b2b    = (const float*)d_in[23];
    const float* b2g    = (const float*)d_in[24];
    const float* b2be   = (const float*)d_in[25];
    const float* b3w    = (const float*)d_in[26];
    const float* b3b    = (const float*)d_in[27];
    const float* b3g    = (const float*)d_in[28];
    const float* b3be   = (const float*)d_in[29];
    float* out = (float*)d_out;

    void *xm, *Tm, *pts, *feats, *bufA, *bufB, *a3a, *a3b, *a3c, *w3;
    cudaGetSymbolAddress(&xm,    g_xmax);
    cudaGetSymbolAddress(&Tm,    g_T);
    cudaGetSymbolAddress(&pts,   g_pts);
    cudaGetSymbolAddress(&feats, g_feats);
    cudaGetSymbolAddress(&bufA,  g_bufA);
    cudaGetSymbolAddress(&bufB,  g_bufB);
    cudaGetSymbolAddress(&a3a,   g_a3a);
    cudaGetSymbolAddress(&a3b,   g_a3b);
    cudaGetSymbolAddress(&a3c,   g_a3c);
    cudaGetSymbolAddress(&w3,    g_w3);
    __nv_bfloat16* w3p = (__nv_bfloat16*)w3;

    cudaMemsetAsync(xm, 0, B_ * TU_ * sizeof(float), 0);
    cudaMemsetAsync(out, 0, B_ * 170 * sizeof(float), 0);

    // weight triples (independent of T-net/topk)
    k_convW<<<(576 * 512 + 255) / 256, 256>>>(c1w, w3p + W3_C1, 576, 512);
    k_convW<<<(512 * 512 + 255) / 256, 256>>>(rw,  w3p + W3_R,  512, 512);
    k_convW<<<(512 * 512 + 255) / 256, 256>>>(b1w, w3p + W3_B1, 512, 512);
    k_convW<<<(512 * 256 + 255) / 256, 256>>>(b2w, w3p + W3_B2, 512, 256);

    // T-net
    k_tnet_conv_max<<<dim3(B_, 8), TU_>>>(points, tw, tb, tg1, tbt1, (float*)xm);
    k_tnet_dense<<<B_, TU_>>>((const float*)xm, td1w, td1b, tg2, tbt2, td2w, td2b,
                              (float*)Tm);
    k_transform<<<(B_ * N_ + 255) / 256, 256>>>(points, (const float*)Tm,
                                                (float*)pts);

    // ball query + grouping
    k_topk<<<dim3(N_ / QB, B_), 256>>>((const float*)pts, noise, (float*)feats);

    // feats -> bf16 triple
    k_convA<<<(M_ * 576 + 255) / 256, 256>>>((const float*)feats,
                                             (__nv_bfloat16*)a3a, 576, M_ * 576);

    // conv1: a3a x c1w3 -> BN+ReLU -> bufA(fp32) + a3b(triple)
    k_mma<1><<<dim3(4, M_ / 128), 256>>>((const __nv_bfloat16*)a3a, w3p + W3_C1,
                                         c1b, g1, be1, nullptr,
                                         (float*)bufA, (__nv_bfloat16*)a3b,
                                         512, 1728, 512);
    // resid: a3b x rw3 + rb + bufA -> a3c(triple)
    k_mma<2><<<dim3(4, M_ / 128), 256>>>((const __nv_bfloat16*)a3b, w3p + W3_R,
                                         rb, nullptr, nullptr, (const float*)bufA,
                                         nullptr, (__nv_bfloat16*)a3c,
                                         512, 1536, 512);
    // b1: a3c x b1w3 -> BN+ReLU -> a3b(triple)
    k_mma<1><<<dim3(4, M_ / 128), 256>>>((const __nv_bfloat16*)a3c, w3p + W3_B1,
                                         b1b, b1g, b1be, nullptr,
                                         nullptr, (__nv_bfloat16*)a3b,
                                         512, 1536, 512);
    // b2: a3b x b2w3 -> BN+ReLU -> bufB(fp32)
    k_mma<1><<<dim3(2, M_ / 128), 256>>>((const __nv_bfloat16*)a3b, w3p + W3_B2,
                                         b2b, b2g, b2be, nullptr,
                                         (float*)bufB, nullptr,
                                         256, 1536, 256);
    // b3 + fused max-pool (SIMT, fp32): bufB x b3w -> atomicMax out[8,170]
    k_gemm128<3><<<dim3(2, M_ / 128), 256>>>((const float*)bufB, b3w, b3b, b3g,
                                             b3be, nullptr, out,
                                             M_, 170, 256);
}